// round 7
// baseline (speedup 1.0000x reference)
#include <cuda_runtime.h>
#include <cuda_bf16.h>
#include <math.h>
#include <stdint.h>

// ---------------- model dims ----------------
#define D_IN     63
#define D_MODEL  256
#define N_CLS    14
#define NL       4
#define D_INNER  512
#define D_STATE  128
#define NH       8
#define HP       64
#define DCONV    4
#define CONV_CH  768          // D_INNER + 2*D_STATE
#define PROJ     1288         // 2*D_INNER + 2*D_STATE + NH
#define PROJ_PAD 1408         // padded to multiple of 128 for GEMM N tiles
#define BATCH    32
#define SEQ      1024
#define TOKENS   (BATCH*SEQ)  // 32768
#define EPS      1e-5f
#define TBLK     8            // scan timesteps per pipeline chunk
#define PSL      16           // p-slice per scan block (HP/4)

// ---------------- scratch (device globals; no allocation allowed) ----------------
__device__ float g_h   [TOKENS * D_MODEL];   // residual stream fp32
__device__ float g_zx  [TOKENS * PROJ];      // zxbcdt fp32
__device__ float g_conv[TOKENS * CONV_CH];   // conv+silu output
__device__ float g_y   [TOKENS * D_INNER];   // scan output fp32
__device__ float g_m   [TOKENS * D_MODEL];   // out-proj result
__device__ float2 g_dtA[BATCH * NH * SEQ];   // (softplus(dt), exp(A*dt))

// bf16 split activations
__device__ __nv_bfloat16 g_hh[TOKENS * D_MODEL];
__device__ __nv_bfloat16 g_hl[TOKENS * D_MODEL];
__device__ __nv_bfloat16 g_yh[TOKENS * D_INNER];
__device__ __nv_bfloat16 g_yl[TOKENS * D_INNER];
// bf16 split weights (inproj padded to 1408 rows, zero-filled)
__device__ __nv_bfloat16 g_wih[NL * PROJ_PAD * D_MODEL];
__device__ __nv_bfloat16 g_wil[NL * PROJ_PAD * D_MODEL];
__device__ __nv_bfloat16 g_woh[NL * D_MODEL * D_INNER];
__device__ __nv_bfloat16 g_wol[NL * D_MODEL * D_INNER];

// ---------------- utils ----------------
__device__ __forceinline__ float block_sum256(float v) {
    __shared__ float sh[8];
    int lane = threadIdx.x & 31;
    int wid  = threadIdx.x >> 5;
#pragma unroll
    for (int o = 16; o > 0; o >>= 1) v += __shfl_xor_sync(0xffffffffu, v, o);
    if (lane == 0) sh[wid] = v;
    __syncthreads();
    float t = sh[0]+sh[1]+sh[2]+sh[3]+sh[4]+sh[5]+sh[6]+sh[7];
    __syncthreads();
    return t;
}

__device__ __forceinline__ float silu_f(float x) {
    return x / (1.0f + expf(-x));
}

__device__ __forceinline__ void split_store(float v, __nv_bfloat16* hi, __nv_bfloat16* lo, size_t idx) {
    __nv_bfloat16 h = __float2bfloat16(v);
    hi[idx] = h;
    lo[idx] = __float2bfloat16(v - __bfloat162float(h));
}

// packed f32x2 helpers
__device__ __forceinline__ unsigned long long f2pack(float a, float b) {
    unsigned long long r;
    asm("mov.b64 %0, {%1, %2};" : "=l"(r) : "f"(a), "f"(b));
    return r;
}
__device__ __forceinline__ unsigned long long fma2(unsigned long long a, unsigned long long b, unsigned long long c) {
    unsigned long long d;
    asm("fma.rn.f32x2 %0, %1, %2, %3;" : "=l"(d) : "l"(a), "l"(b), "l"(c));
    return d;
}
__device__ __forceinline__ unsigned long long mul2(unsigned long long a, unsigned long long b) {
    unsigned long long d;
    asm("mul.rn.f32x2 %0, %1, %2;" : "=l"(d) : "l"(a), "l"(b));
    return d;
}
__device__ __forceinline__ float f2sum(unsigned long long v) {
    float lo, hi;
    asm("mov.b64 {%0, %1}, %2;" : "=f"(lo), "=f"(hi) : "l"(v));
    return lo + hi;
}

__device__ __forceinline__ void cp16(uint32_t dst, const void* src) {
    asm volatile("cp.async.cg.shared.global [%0], [%1], 16;\n" :: "r"(dst), "l"(src));
}

// ---------------- weight conversion (cheap, once per launch) ----------------
__global__ void convert_wi_kernel(const float* __restrict__ w,
                                  __nv_bfloat16* __restrict__ hi, __nv_bfloat16* __restrict__ lo)
{
    int l = blockIdx.y;
    int n = blockIdx.x;
    int k = threadIdx.x;
    float v = (n < PROJ) ? w[((size_t)l * PROJ + n) * D_MODEL + k] : 0.0f;
    size_t o = ((size_t)l * PROJ_PAD + n) * D_MODEL + k;
    __nv_bfloat16 h = __float2bfloat16(v);
    hi[o] = h;
    lo[o] = __float2bfloat16(v - __bfloat162float(h));
}

__global__ void convert_wo_kernel(const float* __restrict__ w,
                                  __nv_bfloat16* __restrict__ hi, __nv_bfloat16* __restrict__ lo)
{
    int l = blockIdx.y;
    size_t idx = (size_t)blockIdx.x * 256 + threadIdx.x;
    size_t o = (size_t)l * D_MODEL * D_INNER + idx;
    float v = w[o];
    __nv_bfloat16 h = __float2bfloat16(v);
    hi[o] = h;
    lo[o] = __float2bfloat16(v - __bfloat162float(h));
}

// ---------------- K0: embed + input layernorm (+ bf16 split out) ----------------
__global__ void __launch_bounds__(256) embed_ln_kernel(
    const float* __restrict__ x, const float* __restrict__ w,
    const float* __restrict__ b, const float* __restrict__ lw,
    const float* __restrict__ lb, float* __restrict__ out,
    __nv_bfloat16* __restrict__ ohi, __nv_bfloat16* __restrict__ olo)
{
    int row = blockIdx.x;
    int tid = threadIdx.x;
    __shared__ float sx[D_IN];
    if (tid < D_IN) sx[tid] = x[(size_t)row * D_IN + tid];
    __syncthreads();
    float acc = b[tid];
    const float* wr = w + (size_t)tid * D_IN;
#pragma unroll
    for (int k = 0; k < D_IN; k++) acc = fmaf(wr[k], sx[k], acc);
    float mean = block_sum256(acc) * (1.0f / 256.0f);
    float d = acc - mean;
    float var = block_sum256(d * d) * (1.0f / 256.0f);
    float v = d * rsqrtf(var + EPS) * lw[tid] + lb[tid];
    size_t idx = (size_t)row * D_MODEL + tid;
    out[idx] = v;
    split_store(v, ohi, olo, idx);
}

// ---------------- K1: split-bf16 tensor-core GEMM ----------------
#define SSTRIDE 40
#define BUFB    (128*SSTRIDE*2)
#define STAGEB  (4*BUFB)
#define GEMM_SMEM (2*STAGEB)

__device__ __forceinline__ void ldsm4(uint32_t* r, uint32_t addr) {
    asm volatile("ldmatrix.sync.aligned.m8n8.x4.shared.b16 {%0,%1,%2,%3}, [%4];"
                 : "=r"(r[0]), "=r"(r[1]), "=r"(r[2]), "=r"(r[3]) : "r"(addr));
}
__device__ __forceinline__ void mma_bf16(float* c, const uint32_t* a, const uint32_t* b) {
    asm volatile("mma.sync.aligned.m16n8k16.row.col.f32.bf16.bf16.f32 "
                 "{%0,%1,%2,%3}, {%4,%5,%6,%7}, {%8,%9}, {%0,%1,%2,%3};"
                 : "+f"(c[0]), "+f"(c[1]), "+f"(c[2]), "+f"(c[3])
                 : "r"(a[0]), "r"(a[1]), "r"(a[2]), "r"(a[3]), "r"(b[0]), "r"(b[1]));
}

__global__ void __launch_bounds__(256, 2) gemm_bf16_split(
    const __nv_bfloat16* __restrict__ Ahi, const __nv_bfloat16* __restrict__ Alo,
    const __nv_bfloat16* __restrict__ Whi, const __nv_bfloat16* __restrict__ Wlo,
    float* __restrict__ C, int N, int K)
{
    extern __shared__ char smem[];
    const int tid  = threadIdx.x;
    const int lane = tid & 31;
    const int warp = tid >> 5;
    const int wm = warp >> 2;
    const int wn = warp & 3;
    const int m0 = blockIdx.x * 128;
    const int n0 = blockIdx.y * 128;

    const uint32_t sbase = (uint32_t)__cvta_generic_to_shared(smem);
    const int lr = tid >> 2;
    const int lc = tid & 3;

    float acc[4][4][4];
#pragma unroll
    for (int i = 0; i < 4; i++)
#pragma unroll
        for (int j = 0; j < 4; j++)
#pragma unroll
            for (int q = 0; q < 4; q++) acc[i][j][q] = 0.0f;

    const int nst = K >> 5;
    {
        uint32_t st = sbase;
#pragma unroll
        for (int hh = 0; hh < 2; hh++) {
            int r = lr + hh * 64;
            size_t ga = (size_t)(m0 + r) * K + lc * 8;
            size_t gw = (size_t)(n0 + r) * K + lc * 8;
            uint32_t sa = st + (uint32_t)(r * SSTRIDE + lc * 8) * 2;
            cp16(sa,          Ahi + ga);
            cp16(sa + BUFB,   Alo + ga);
            cp16(sa + 2*BUFB, Whi + gw);
            cp16(sa + 3*BUFB, Wlo + gw);
        }
    }
    asm volatile("cp.async.commit_group;\n");

    for (int s = 0; s < nst; s++) {
        if (s + 1 < nst) {
            int k0 = (s + 1) << 5;
            uint32_t st = sbase + ((s + 1) & 1) * STAGEB;
#pragma unroll
            for (int hh = 0; hh < 2; hh++) {
                int r = lr + hh * 64;
                size_t ga = (size_t)(m0 + r) * K + k0 + lc * 8;
                size_t gw = (size_t)(n0 + r) * K + k0 + lc * 8;
                uint32_t sa = st + (uint32_t)(r * SSTRIDE + lc * 8) * 2;
                cp16(sa,          Ahi + ga);
                cp16(sa + BUFB,   Alo + ga);
                cp16(sa + 2*BUFB, Whi + gw);
                cp16(sa + 3*BUFB, Wlo + gw);
            }
        }
        asm volatile("cp.async.commit_group;\n");
        asm volatile("cp.async.wait_group 1;\n");
        __syncthreads();

        uint32_t st = sbase + (s & 1) * STAGEB;
        uint32_t aBase = st + (uint32_t)((wm * 64 + (lane & 15)) * SSTRIDE + (lane >> 4) * 8) * 2;
        uint32_t bBase = st + 2*BUFB +
            (uint32_t)((wn * 32 + ((lane & 7) + (lane >> 4) * 8)) * SSTRIDE + ((lane >> 3) & 1) * 8) * 2;

#pragma unroll
        for (int kk = 0; kk < 32; kk += 16) {
            uint32_t af[4][4], bh[2][4], bl[2][4];
#pragma unroll
            for (int mt = 0; mt < 4; mt++)
                ldsm4(af[mt], aBase + (uint32_t)(mt * 16 * SSTRIDE + kk) * 2);
#pragma unroll
            for (int p = 0; p < 2; p++) {
                ldsm4(bh[p], bBase + (uint32_t)(p * 16 * SSTRIDE + kk) * 2);
                ldsm4(bl[p], bBase + BUFB + (uint32_t)(p * 16 * SSTRIDE + kk) * 2);
            }
#pragma unroll
            for (int mt = 0; mt < 4; mt++)
#pragma unroll
                for (int nt = 0; nt < 4; nt++) {
                    mma_bf16(acc[mt][nt], af[mt], &bh[nt >> 1][(nt & 1) * 2]);
                    mma_bf16(acc[mt][nt], af[mt], &bl[nt >> 1][(nt & 1) * 2]);
                }
#pragma unroll
            for (int mt = 0; mt < 4; mt++)
                ldsm4(af[mt], aBase + BUFB + (uint32_t)(mt * 16 * SSTRIDE + kk) * 2);
#pragma unroll
            for (int mt = 0; mt < 4; mt++)
#pragma unroll
                for (int nt = 0; nt < 4; nt++)
                    mma_bf16(acc[mt][nt], af[mt], &bh[nt >> 1][(nt & 1) * 2]);
        }
        __syncthreads();
    }

    const int mrow = m0 + wm * 64 + (lane >> 2);
    const int nc0  = n0 + wn * 32 + (lane & 3) * 2;
#pragma unroll
    for (int mt = 0; mt < 4; mt++) {
#pragma unroll
        for (int nt = 0; nt < 4; nt++) {
            int n = nc0 + nt * 8;
            if (n < N) {
                int m = mrow + mt * 16;
                float2 v0 = make_float2(acc[mt][nt][0], acc[mt][nt][1]);
                float2 v1 = make_float2(acc[mt][nt][2], acc[mt][nt][3]);
                *(float2*)&C[(size_t)m * N + n]       = v0;
                *(float2*)&C[(size_t)(m + 8) * N + n] = v1;
            }
        }
    }
}

// ---------------- K2: causal depthwise conv (4 taps) + silu ----------------
__global__ void conv_silu_kernel(
    const float* __restrict__ zx, const float* __restrict__ cw,
    const float* __restrict__ cb, float* __restrict__ out)
{
    int c = blockIdx.x * 256 + threadIdx.x;
    int l = blockIdx.y;
    int b = blockIdx.z;
    const float* col = zx + (size_t)b * SEQ * PROJ + D_INNER + c;
    float acc = cb[c];
#pragma unroll
    for (int k = 0; k < 4; k++) {
        int li = l + k - 3;
        if (li >= 0) acc = fmaf(cw[k * CONV_CH + c], col[(size_t)li * PROJ], acc);
    }
    out[((size_t)b * SEQ + l) * CONV_CH + c] = silu_f(acc);
}

// ---------------- K2b: dt precompute ----------------
__global__ void __launch_bounds__(256) dt_kernel(
    const float* __restrict__ zx, const float* __restrict__ dt_bias,
    const float* __restrict__ A_log, float2* __restrict__ dtA)
{
    int idx = blockIdx.x * 256 + threadIdx.x;
    int t  = idx & (SEQ - 1);
    int bh = idx >> 10;
    int h  = bh & (NH - 1);
    int b  = bh >> 3;
    float Ah = -expf(A_log[h]);
    float xdt = zx[((size_t)b * SEQ + t) * PROJ + (D_INNER + CONV_CH) + h] + dt_bias[h];
    float sp = fmaxf(xdt, 0.0f) + log1pf(expf(-fabsf(xdt)));
    dtA[idx] = make_float2(sp, expf(Ah * sp));
}

// ---------------- K3: p-split SSM scan, f32x2, LDS.128, cp.async pipelined ----------
// grid (NH, BATCH, 4): each block handles 16 of 64 head-dim slots, all 128 n.
// 128 threads: pl = tid&15, nchunk = tid>>4 (8 chunks x 16 n -> st2[8]/thread)
#define SST_F (TBLK*16 + TBLK*128 + TBLK*128 + TBLK*2)   // 2192 floats per stage
#define SCAN_SMEM ((2*SST_F + TBLK*128) * 4)             // + syp[8][8][16] = 21632 B

__global__ void __launch_bounds__(128) scan_kernel(
    const float* __restrict__ conv,    // [TOKENS, 768]
    const float2* __restrict__ dtA,    // [B*NH*SEQ]
    const float* __restrict__ Dp,      // [8]
    float* __restrict__ yout)          // [TOKENS, 512]
{
    extern __shared__ float sm[];
    float* stage0 = sm;
    float* stage1 = sm + SST_F;
    float* syp    = sm + 2 * SST_F;    // [t][nchunk][pl]

    const int h  = blockIdx.x;
    const int b  = blockIdx.y;
    const int ps = blockIdx.z;
    const int tid = threadIdx.x;
    const int nchunk = tid >> 4;       // 0..7
    const int pl = tid & 15;

    const float Dh = Dp[h];

    unsigned long long st2[8];
#pragma unroll
    for (int j = 0; j < 8; j++) st2[j] = 0ull;

    const float* convb = conv + (size_t)b * SEQ * CONV_CH;
    const float* dtAb  = (const float*)(dtA + (size_t)(b * NH + h) * SEQ);
    float* yb = yout + (size_t)b * SEQ * D_INNER + h * HP + ps * PSL;

    const uint32_t sb0 = (uint32_t)__cvta_generic_to_shared(stage0);
    const uint32_t sb1 = (uint32_t)__cvta_generic_to_shared(stage1);

    // per-stage float offsets
    const int OX = 0;                  // x[8][16]
    const int OB = TBLK * 16;          // B[8][128]
    const int OC = OB + TBLK * 128;    // C[8][128]
    const int OD = OC + TBLK * 128;    // dtA[8][2]

    // prefetch chunk c: 548 cp16 items over 128 threads
    auto prefetch = [&](int c) {
        int t0 = c * TBLK;
        uint32_t sb = (c & 1) ? sb1 : sb0;
#pragma unroll
        for (int i = 0; i < 5; i++) {
            int it = i * 128 + tid;
            if (it < 256) {                 // B
                int t = it >> 5, q = it & 31;
                cp16(sb + (uint32_t)(OB + t * 128 + q * 4) * 4,
                     convb + (size_t)(t0 + t) * CONV_CH + D_INNER + q * 4);
            } else if (it < 512) {          // C
                int j = it - 256;
                int t = j >> 5, q = j & 31;
                cp16(sb + (uint32_t)(OC + t * 128 + q * 4) * 4,
                     convb + (size_t)(t0 + t) * CONV_CH + D_INNER + D_STATE + q * 4);
            } else if (it < 544) {          // x slice
                int j = it - 512;
                int t = j >> 2, q = j & 3;
                cp16(sb + (uint32_t)(OX + t * 16 + q * 4) * 4,
                     convb + (size_t)(t0 + t) * CONV_CH + h * HP + ps * PSL + q * 4);
            } else if (it < 548) {          // dtA (8 float2 = 16 floats)
                int j = it - 544;
                cp16(sb + (uint32_t)(OD + j * 4) * 4, dtAb + (size_t)t0 * 2 + j * 4);
            }
        }
    };

    const int NCHUNKS = SEQ / TBLK;    // 128

    prefetch(0);
    asm volatile("cp.async.commit_group;\n");

    for (int c = 0; c < NCHUNKS; c++) {
        if (c + 1 < NCHUNKS) prefetch(c + 1);
        asm volatile("cp.async.commit_group;\n");
        asm volatile("cp.async.wait_group 1;\n");
        __syncthreads();

        const float* stg = (c & 1) ? stage1 : stage0;
        const unsigned long long* sBu = (const unsigned long long*)(stg + OB);
        const unsigned long long* sCu = (const unsigned long long*)(stg + OC);
        const float* sdd = stg + OD;
        const float* sx  = stg + OX;

#pragma unroll
        for (int t = 0; t < TBLK; t++) {
            float dtp = sdd[t * 2];
            float dA  = sdd[t * 2 + 1];
            float dtx = dtp * sx[t * 16 + pl];
            unsigned long long dA2  = f2pack(dA, dA);
            unsigned long long dtx2 = f2pack(dtx, dtx);
            unsigned long long acc2 = 0ull;
            const ulonglong2* Bp = (const ulonglong2*)(sBu + t * 64) + nchunk * 4;
            const ulonglong2* Cp = (const ulonglong2*)(sCu + t * 64) + nchunk * 4;
#pragma unroll
            for (int j = 0; j < 4; j++) {
                ulonglong2 bq = Bp[j];
                ulonglong2 cq = Cp[j];
                st2[2*j]   = fma2(st2[2*j],   dA2, mul2(dtx2, bq.x));
                acc2       = fma2(st2[2*j],   cq.x, acc2);
                st2[2*j+1] = fma2(st2[2*j+1], dA2, mul2(dtx2, bq.y));
                acc2       = fma2(st2[2*j+1], cq.y, acc2);
            }
            syp[t * 128 + nchunk * 16 + pl] = f2sum(acc2);
        }
        __syncthreads();

        // write y: one value per thread (t = tid>>4, pp = tid&15)
        {
            int t0 = c * TBLK;
            int t  = tid >> 4;
            int pp = tid & 15;
            float v = Dh * sx[t * 16 + pp];
#pragma unroll
            for (int nc = 0; nc < 8; nc++) v += syp[t * 128 + nc * 16 + pp];
            yb[(size_t)(t0 + t) * D_INNER + pp] = v;
        }
        __syncthreads();
    }
}

// ---------------- K4: gate + RMSNorm -> bf16 split ----------------
__global__ void __launch_bounds__(256) gate_rms_kernel(
    const float* __restrict__ y, const float* __restrict__ zx,
    const float* __restrict__ nw,
    __nv_bfloat16* __restrict__ yhi, __nv_bfloat16* __restrict__ ylo)
{
    int row = blockIdx.x;
    int tid = threadIdx.x;
    const float* yr = y + (size_t)row * D_INNER;
    const float* zr = zx + (size_t)row * PROJ;
    float v0 = yr[tid], v1 = yr[tid + 256];
    float z0 = zr[tid], z1 = zr[tid + 256];
    float g0 = v0 * silu_f(z0);
    float g1 = v1 * silu_f(z1);
    float ss = block_sum256(g0 * g0 + g1 * g1);
    float r = rsqrtf(ss * (1.0f / 512.0f) + EPS);
    size_t base = (size_t)row * D_INNER;
    split_store(g0 * r * nw[tid],       yhi, ylo, base + tid);
    split_store(g1 * r * nw[tid + 256], yhi, ylo, base + tid + 256);
}

// ---------------- K5: residual add + layernorm -> fp32 + bf16 split ----------------
__global__ void __launch_bounds__(256) add_ln_kernel(
    float* __restrict__ h, const float* __restrict__ m,
    const float* __restrict__ w, const float* __restrict__ bvec,
    __nv_bfloat16* __restrict__ hhi, __nv_bfloat16* __restrict__ hlo)
{
    int row = blockIdx.x;
    int tid = threadIdx.x;
    size_t idx = (size_t)row * D_MODEL + tid;
    float v = h[idx] + m[idx];
    float mean = block_sum256(v) * (1.0f / 256.0f);
    float d = v - mean;
    float var = block_sum256(d * d) * (1.0f / 256.0f);
    float o = d * rsqrtf(var + EPS) * w[tid] + bvec[tid];
    h[idx] = o;
    split_store(o, hhi, hlo, idx);
}

// ---------------- K6: masked mean pool + classifier head ----------------
__global__ void __launch_bounds__(256) pool_head_kernel(
    const float* __restrict__ h, const int* __restrict__ lengths,
    const float* __restrict__ hw, const float* __restrict__ hb,
    float* __restrict__ out)
{
    int b = blockIdx.x;
    int tid = threadIdx.x;
    int len = lengths[b];
    const float* hr = h + (size_t)b * SEQ * D_MODEL;
    float a0 = 0.f, a1 = 0.f, a2 = 0.f, a3 = 0.f;
    int l = 0;
    for (; l + 4 <= len; l += 4) {
        a0 += hr[(size_t)(l+0) * D_MODEL + tid];
        a1 += hr[(size_t)(l+1) * D_MODEL + tid];
        a2 += hr[(size_t)(l+2) * D_MODEL + tid];
        a3 += hr[(size_t)(l+3) * D_MODEL + tid];
    }
    for (; l < len; l++) a0 += hr[(size_t)l * D_MODEL + tid];
    float acc = (a0 + a1) + (a2 + a3);
    __shared__ float sp[D_MODEL];
    sp[tid] = acc / (float)len;
    __syncthreads();
    if (tid < N_CLS) {
        float o = hb[tid];
        const float* wr = hw + (size_t)tid * D_MODEL;
#pragma unroll 8
        for (int k = 0; k < D_MODEL; k++) o = fmaf(wr[k], sp[k], o);
        out[b * N_CLS + tid] = o;
    }
}

// ---------------- launch ----------------
extern "C" void kernel_launch(void* const* d_in, const int* in_sizes, int n_in,
                              void* d_out, int out_size)
{
    const float* x        = (const float*)d_in[0];
    const float* in_w     = (const float*)d_in[1];
    const float* in_b     = (const float*)d_in[2];
    const float* lnin_w   = (const float*)d_in[3];
    const float* lnin_b   = (const float*)d_in[4];
    const float* inproj_w = (const float*)d_in[5];
    const float* conv_w   = (const float*)d_in[6];
    const float* conv_b   = (const float*)d_in[7];
    const float* dt_bias  = (const float*)d_in[8];
    const float* A_log    = (const float*)d_in[9];
    const float* Dw       = (const float*)d_in[10];
    const float* norm_w   = (const float*)d_in[11];
    const float* outp_w   = (const float*)d_in[12];
    const float* ln_w     = (const float*)d_in[13];
    const float* ln_b     = (const float*)d_in[14];
    const float* head_w   = (const float*)d_in[15];
    const float* head_b   = (const float*)d_in[16];
    const int*   lengths  = (const int*)d_in[17];
    float* out = (float*)d_out;

    float *ph, *pzx, *pconv, *py, *pm;
    float2* pdtA;
    cudaGetSymbolAddress((void**)&ph,    g_h);
    cudaGetSymbolAddress((void**)&pzx,   g_zx);
    cudaGetSymbolAddress((void**)&pconv, g_conv);
    cudaGetSymbolAddress((void**)&py,    g_y);
    cudaGetSymbolAddress((void**)&pm,    g_m);
    cudaGetSymbolAddress((void**)&pdtA,  g_dtA);
    __nv_bfloat16 *phh, *phl, *pyh, *pyl, *pwih, *pwil, *pwoh, *pwol;
    cudaGetSymbolAddress((void**)&phh,  g_hh);
    cudaGetSymbolAddress((void**)&phl,  g_hl);
    cudaGetSymbolAddress((void**)&pyh,  g_yh);
    cudaGetSymbolAddress((void**)&pyl,  g_yl);
    cudaGetSymbolAddress((void**)&pwih, g_wih);
    cudaGetSymbolAddress((void**)&pwil, g_wil);
    cudaGetSymbolAddress((void**)&pwoh, g_woh);
    cudaGetSymbolAddress((void**)&pwol, g_wol);

    cudaFuncSetAttribute(gemm_bf16_split, cudaFuncAttributeMaxDynamicSharedMemorySize, GEMM_SMEM);
    cudaFuncSetAttribute(scan_kernel, cudaFuncAttributeMaxDynamicSharedMemorySize, SCAN_SMEM);

    convert_wi_kernel<<<dim3(PROJ_PAD, NL), 256>>>(inproj_w, pwih, pwil);
    convert_wo_kernel<<<dim3(D_MODEL * D_INNER / 256, NL), 256>>>(outp_w, pwoh, pwol);

    embed_ln_kernel<<<TOKENS, 256>>>(x, in_w, in_b, lnin_w, lnin_b, ph, phh, phl);

    for (int i = 0; i < NL; i++) {
        gemm_bf16_split<<<dim3(TOKENS / 128, PROJ_PAD / 128), 256, GEMM_SMEM>>>(
            phh, phl,
            pwih + (size_t)i * PROJ_PAD * D_MODEL, pwil + (size_t)i * PROJ_PAD * D_MODEL,
            pzx, PROJ, D_MODEL);

        conv_silu_kernel<<<dim3(CONV_CH / 256, SEQ, BATCH), 256>>>(
            pzx, conv_w + (size_t)i * DCONV * CONV_CH, conv_b + (size_t)i * CONV_CH, pconv);

        dt_kernel<<<BATCH * NH * SEQ / 256, 256>>>(
            pzx, dt_bias + i * NH, A_log + i * NH, pdtA);

        scan_kernel<<<dim3(NH, BATCH, HP / PSL), 128, SCAN_SMEM>>>(
            pconv, pdtA, Dw + i * NH, py);

        gate_rms_kernel<<<TOKENS, 256>>>(py, pzx, norm_w + (size_t)i * D_INNER, pyh, pyl);

        gemm_bf16_split<<<dim3(TOKENS / 128, D_MODEL / 128), 256, GEMM_SMEM>>>(
            pyh, pyl,
            pwoh + (size_t)i * D_MODEL * D_INNER, pwol + (size_t)i * D_MODEL * D_INNER,
            pm, D_MODEL, D_INNER);

        add_ln_kernel<<<TOKENS, 256>>>(ph, pm, ln_w + (size_t)i * D_MODEL,
                                       ln_b + (size_t)i * D_MODEL, phh, phl);
    }

    pool_head_kernel<<<BATCH, 256>>>(ph, lengths, head_w, head_b, out);
}

// round 10
// speedup vs baseline: 1.0093x; 1.0093x over previous
#include <cuda_runtime.h>
#include <cuda_bf16.h>
#include <math.h>
#include <stdint.h>

// ---------------- model dims ----------------
#define D_IN     63
#define D_MODEL  256
#define N_CLS    14
#define NL       4
#define D_INNER  512
#define D_STATE  128
#define NH       8
#define HP       64
#define DCONV    4
#define CONV_CH  768
#define PROJ     1288
#define PROJ_PAD 1408
#define BATCH    32
#define SEQ      1024
#define TOKENS   (BATCH*SEQ)
#define EPS      1e-5f
#define TBLK     8
#define PSL      16

// ---------------- scratch ----------------
__device__ float g_h   [TOKENS * D_MODEL];
__device__ float g_zx  [TOKENS * PROJ];
__device__ float g_conv[TOKENS * CONV_CH];
__device__ float g_y   [TOKENS * D_INNER];
__device__ float g_m   [TOKENS * D_MODEL];
__device__ float2 g_dtA[BATCH * NH * SEQ];

__device__ __nv_bfloat16 g_hh[TOKENS * D_MODEL];
__device__ __nv_bfloat16 g_hl[TOKENS * D_MODEL];
__device__ __nv_bfloat16 g_yh[TOKENS * D_INNER];
__device__ __nv_bfloat16 g_yl[TOKENS * D_INNER];
__device__ __nv_bfloat16 g_wih[NL * PROJ_PAD * D_MODEL];
__device__ __nv_bfloat16 g_wil[NL * PROJ_PAD * D_MODEL];
__device__ __nv_bfloat16 g_woh[NL * D_MODEL * D_INNER];
__device__ __nv_bfloat16 g_wol[NL * D_MODEL * D_INNER];

// ---------------- utils ----------------
__device__ __forceinline__ float block_sum256(float v) {
    __shared__ float sh[8];
    int lane = threadIdx.x & 31;
    int wid  = threadIdx.x >> 5;
#pragma unroll
    for (int o = 16; o > 0; o >>= 1) v += __shfl_xor_sync(0xffffffffu, v, o);
    if (lane == 0) sh[wid] = v;
    __syncthreads();
    float t = sh[0]+sh[1]+sh[2]+sh[3]+sh[4]+sh[5]+sh[6]+sh[7];
    __syncthreads();
    return t;
}

__device__ __forceinline__ float silu_f(float x) {
    return x / (1.0f + expf(-x));
}

__device__ __forceinline__ void split_store(float v, __nv_bfloat16* hi, __nv_bfloat16* lo, size_t idx) {
    __nv_bfloat16 h = __float2bfloat16(v);
    hi[idx] = h;
    lo[idx] = __float2bfloat16(v - __bfloat162float(h));
}

__device__ __forceinline__ unsigned long long f2pack(float a, float b) {
    unsigned long long r;
    asm("mov.b64 %0, {%1, %2};" : "=l"(r) : "f"(a), "f"(b));
    return r;
}
__device__ __forceinline__ unsigned long long fma2(unsigned long long a, unsigned long long b, unsigned long long c) {
    unsigned long long d;
    asm("fma.rn.f32x2 %0, %1, %2, %3;" : "=l"(d) : "l"(a), "l"(b), "l"(c));
    return d;
}
__device__ __forceinline__ unsigned long long mul2(unsigned long long a, unsigned long long b) {
    unsigned long long d;
    asm("mul.rn.f32x2 %0, %1, %2;" : "=l"(d) : "l"(a), "l"(b));
    return d;
}
__device__ __forceinline__ float f2sum(unsigned long long v) {
    float lo, hi;
    asm("mov.b64 {%0, %1}, %2;" : "=f"(lo), "=f"(hi) : "l"(v));
    return lo + hi;
}

__device__ __forceinline__ void cp16(uint32_t dst, const void* src) {
    asm volatile("cp.async.cg.shared.global [%0], [%1], 16;\n" :: "r"(dst), "l"(src));
}

// ---------------- weight conversion ----------------
__global__ void convert_wi_kernel(const float* __restrict__ w,
                                  __nv_bfloat16* __restrict__ hi, __nv_bfloat16* __restrict__ lo)
{
    int l = blockIdx.y;
    int n = blockIdx.x;
    int k = threadIdx.x;
    float v = (n < PROJ) ? w[((size_t)l * PROJ + n) * D_MODEL + k] : 0.0f;
    size_t o = ((size_t)l * PROJ_PAD + n) * D_MODEL + k;
    __nv_bfloat16 h = __float2bfloat16(v);
    hi[o] = h;
    lo[o] = __float2bfloat16(v - __bfloat162float(h));
}

__global__ void convert_wo_kernel(const float* __restrict__ w,
                                  __nv_bfloat16* __restrict__ hi, __nv_bfloat16* __restrict__ lo)
{
    int l = blockIdx.y;
    size_t idx = (size_t)blockIdx.x * 256 + threadIdx.x;
    size_t o = (size_t)l * D_MODEL * D_INNER + idx;
    float v = w[o];
    __nv_bfloat16 h = __float2bfloat16(v);
    hi[o] = h;
    lo[o] = __float2bfloat16(v - __bfloat162float(h));
}

// ---------------- K0: embed + input layernorm ----------------
__global__ void __launch_bounds__(256) embed_ln_kernel(
    const float* __restrict__ x, const float* __restrict__ w,
    const float* __restrict__ b, const float* __restrict__ lw,
    const float* __restrict__ lb, float* __restrict__ out,
    __nv_bfloat16* __restrict__ ohi, __nv_bfloat16* __restrict__ olo)
{
    int row = blockIdx.x;
    int tid = threadIdx.x;
    __shared__ float sx[D_IN];
    if (tid < D_IN) sx[tid] = x[(size_t)row * D_IN + tid];
    __syncthreads();
    float acc = b[tid];
    const float* wr = w + (size_t)tid * D_IN;
#pragma unroll
    for (int k = 0; k < D_IN; k++) acc = fmaf(wr[k], sx[k], acc);
    float mean = block_sum256(acc) * (1.0f / 256.0f);
    float d = acc - mean;
    float var = block_sum256(d * d) * (1.0f / 256.0f);
    float v = d * rsqrtf(var + EPS) * lw[tid] + lb[tid];
    size_t idx = (size_t)row * D_MODEL + tid;
    out[idx] = v;
    split_store(v, ohi, olo, idx);
}

// ---------------- K1: split-bf16 tensor-core GEMM (mma.sync) ----------------
#define SSTRIDE 40
#define BUFB    (128*SSTRIDE*2)
#define STAGEB  (4*BUFB)
#define GEMM_SMEM (2*STAGEB)

__device__ __forceinline__ void ldsm4(uint32_t* r, uint32_t addr) {
    asm volatile("ldmatrix.sync.aligned.m8n8.x4.shared.b16 {%0,%1,%2,%3}, [%4];"
                 : "=r"(r[0]), "=r"(r[1]), "=r"(r[2]), "=r"(r[3]) : "r"(addr));
}
__device__ __forceinline__ void mma_bf16(float* c, const uint32_t* a, const uint32_t* b) {
    asm volatile("mma.sync.aligned.m16n8k16.row.col.f32.bf16.bf16.f32 "
                 "{%0,%1,%2,%3}, {%4,%5,%6,%7}, {%8,%9}, {%0,%1,%2,%3};"
                 : "+f"(c[0]), "+f"(c[1]), "+f"(c[2]), "+f"(c[3])
                 : "r"(a[0]), "r"(a[1]), "r"(a[2]), "r"(a[3]), "r"(b[0]), "r"(b[1]));
}

__global__ void __launch_bounds__(256, 2) gemm_bf16_split(
    const __nv_bfloat16* __restrict__ Ahi, const __nv_bfloat16* __restrict__ Alo,
    const __nv_bfloat16* __restrict__ Whi, const __nv_bfloat16* __restrict__ Wlo,
    float* __restrict__ C, int N, int K)
{
    extern __shared__ char smem[];
    const int tid  = threadIdx.x;
    const int lane = tid & 31;
    const int warp = tid >> 5;
    const int wm = warp >> 2;
    const int wn = warp & 3;
    const int m0 = blockIdx.x * 128;
    const int n0 = blockIdx.y * 128;

    const uint32_t sbase = (uint32_t)__cvta_generic_to_shared(smem);
    const int lr = tid >> 2;
    const int lc = tid & 3;

    float acc[4][4][4];
#pragma unroll
    for (int i = 0; i < 4; i++)
#pragma unroll
        for (int j = 0; j < 4; j++)
#pragma unroll
            for (int q = 0; q < 4; q++) acc[i][j][q] = 0.0f;

    const int nst = K >> 5;
    {
        uint32_t st = sbase;
#pragma unroll
        for (int hh = 0; hh < 2; hh++) {
            int r = lr + hh * 64;
            size_t ga = (size_t)(m0 + r) * K + lc * 8;
            size_t gw = (size_t)(n0 + r) * K + lc * 8;
            uint32_t sa = st + (uint32_t)(r * SSTRIDE + lc * 8) * 2;
            cp16(sa,          Ahi + ga);
            cp16(sa + BUFB,   Alo + ga);
            cp16(sa + 2*BUFB, Whi + gw);
            cp16(sa + 3*BUFB, Wlo + gw);
        }
    }
    asm volatile("cp.async.commit_group;\n");

    for (int s = 0; s < nst; s++) {
        if (s + 1 < nst) {
            int k0 = (s + 1) << 5;
            uint32_t st = sbase + ((s + 1) & 1) * STAGEB;
#pragma unroll
            for (int hh = 0; hh < 2; hh++) {
                int r = lr + hh * 64;
                size_t ga = (size_t)(m0 + r) * K + k0 + lc * 8;
                size_t gw = (size_t)(n0 + r) * K + k0 + lc * 8;
                uint32_t sa = st + (uint32_t)(r * SSTRIDE + lc * 8) * 2;
                cp16(sa,          Ahi + ga);
                cp16(sa + BUFB,   Alo + ga);
                cp16(sa + 2*BUFB, Whi + gw);
                cp16(sa + 3*BUFB, Wlo + gw);
            }
        }
        asm volatile("cp.async.commit_group;\n");
        asm volatile("cp.async.wait_group 1;\n");
        __syncthreads();

        uint32_t st = sbase + (s & 1) * STAGEB;
        uint32_t aBase = st + (uint32_t)((wm * 64 + (lane & 15)) * SSTRIDE + (lane >> 4) * 8) * 2;
        uint32_t bBase = st + 2*BUFB +
            (uint32_t)((wn * 32 + ((lane & 7) + (lane >> 4) * 8)) * SSTRIDE + ((lane >> 3) & 1) * 8) * 2;

#pragma unroll
        for (int kk = 0; kk < 32; kk += 16) {
            uint32_t af[4][4], bh[2][4], bl[2][4];
#pragma unroll
            for (int mt = 0; mt < 4; mt++)
                ldsm4(af[mt], aBase + (uint32_t)(mt * 16 * SSTRIDE + kk) * 2);
#pragma unroll
            for (int p = 0; p < 2; p++) {
                ldsm4(bh[p], bBase + (uint32_t)(p * 16 * SSTRIDE + kk) * 2);
                ldsm4(bl[p], bBase + BUFB + (uint32_t)(p * 16 * SSTRIDE + kk) * 2);
            }
#pragma unroll
            for (int mt = 0; mt < 4; mt++)
#pragma unroll
                for (int nt = 0; nt < 4; nt++) {
                    mma_bf16(acc[mt][nt], af[mt], &bh[nt >> 1][(nt & 1) * 2]);
                    mma_bf16(acc[mt][nt], af[mt], &bl[nt >> 1][(nt & 1) * 2]);
                }
#pragma unroll
            for (int mt = 0; mt < 4; mt++)
                ldsm4(af[mt], aBase + BUFB + (uint32_t)(mt * 16 * SSTRIDE + kk) * 2);
#pragma unroll
            for (int mt = 0; mt < 4; mt++)
#pragma unroll
                for (int nt = 0; nt < 4; nt++)
                    mma_bf16(acc[mt][nt], af[mt], &bh[nt >> 1][(nt & 1) * 2]);
        }
        __syncthreads();
    }

    const int mrow = m0 + wm * 64 + (lane >> 2);
    const int nc0  = n0 + wn * 32 + (lane & 3) * 2;
#pragma unroll
    for (int mt = 0; mt < 4; mt++) {
#pragma unroll
        for (int nt = 0; nt < 4; nt++) {
            int n = nc0 + nt * 8;
            if (n < N) {
                int m = mrow + mt * 16;
                float2 v0 = make_float2(acc[mt][nt][0], acc[mt][nt][1]);
                float2 v1 = make_float2(acc[mt][nt][2], acc[mt][nt][3]);
                *(float2*)&C[(size_t)m * N + n]       = v0;
                *(float2*)&C[(size_t)(m + 8) * N + n] = v1;
            }
        }
    }
}

// ---------------- K2: causal depthwise conv + silu, register sliding window ----
// grid (3, 8, BATCH): thread owns channel c, walks 128-step L segment.
// each zx element read exactly once (+3-row halo per segment).
#define LSEG 128
__global__ void __launch_bounds__(256) conv_silu_kernel(
    const float* __restrict__ zx, const float* __restrict__ cw,
    const float* __restrict__ cb, float* __restrict__ out)
{
    int c = blockIdx.x * 256 + threadIdx.x;     // 0..767
    int l0 = blockIdx.y * LSEG;
    int b = blockIdx.z;
    const float* col = zx + (size_t)b * SEQ * PROJ + D_INNER + c;
    const float w0 = cw[c];
    const float w1 = cw[CONV_CH + c];
    const float w2 = cw[2 * CONV_CH + c];
    const float w3 = cw[3 * CONV_CH + c];
    const float bias = cb[c];

    float x0 = 0.f, x1 = 0.f, x2 = 0.f;
    if (l0 > 0) {
        x0 = col[(size_t)(l0 - 3) * PROJ];
        x1 = col[(size_t)(l0 - 2) * PROJ];
        x2 = col[(size_t)(l0 - 1) * PROJ];
    }
    float* orow = out + ((size_t)b * SEQ + l0) * CONV_CH + c;
    const float* irow = col + (size_t)l0 * PROJ;
#pragma unroll 4
    for (int i = 0; i < LSEG; i++) {
        float x3 = irow[(size_t)i * PROJ];
        float acc = bias;
        acc = fmaf(w0, x0, acc);
        acc = fmaf(w1, x1, acc);
        acc = fmaf(w2, x2, acc);
        acc = fmaf(w3, x3, acc);
        orow[(size_t)i * CONV_CH] = silu_f(acc);
        x0 = x1; x1 = x2; x2 = x3;
    }
}

// ---------------- K2b: dt precompute ----------------
__global__ void __launch_bounds__(256) dt_kernel(
    const float* __restrict__ zx, const float* __restrict__ dt_bias,
    const float* __restrict__ A_log, float2* __restrict__ dtA)
{
    int idx = blockIdx.x * 256 + threadIdx.x;
    int t  = idx & (SEQ - 1);
    int bh = idx >> 10;
    int h  = bh & (NH - 1);
    int b  = bh >> 3;
    float Ah = -expf(A_log[h]);
    float xdt = zx[((size_t)b * SEQ + t) * PROJ + (D_INNER + CONV_CH) + h] + dt_bias[h];
    float sp = fmaxf(xdt, 0.0f) + log1pf(expf(-fabsf(xdt)));
    dtA[idx] = make_float2(sp, expf(Ah * sp));
}

// ---------------- K3: p-split SSM scan ----------------
#define SST_F (TBLK*16 + TBLK*128 + TBLK*128 + TBLK*2)
#define SCAN_SMEM ((2*SST_F + TBLK*128) * 4)

__global__ void __launch_bounds__(128) scan_kernel(
    const float* __restrict__ conv,
    const float2* __restrict__ dtA,
    const float* __restrict__ Dp,
    float* __restrict__ yout)
{
    extern __shared__ float sm[];
    float* stage0 = sm;
    float* stage1 = sm + SST_F;
    float* syp    = sm + 2 * SST_F;

    const int h  = blockIdx.x;
    const int b  = blockIdx.y;
    const int ps = blockIdx.z;
    const int tid = threadIdx.x;
    const int nchunk = tid >> 4;
    const int pl = tid & 15;

    const float Dh = Dp[h];

    unsigned long long st2[8];
#pragma unroll
    for (int j = 0; j < 8; j++) st2[j] = 0ull;

    const float* convb = conv + (size_t)b * SEQ * CONV_CH;
    const float* dtAb  = (const float*)(dtA + (size_t)(b * NH + h) * SEQ);
    float* yb = yout + (size_t)b * SEQ * D_INNER + h * HP + ps * PSL;

    const uint32_t sb0 = (uint32_t)__cvta_generic_to_shared(stage0);
    const uint32_t sb1 = (uint32_t)__cvta_generic_to_shared(stage1);

    const int OX = 0;
    const int OB = TBLK * 16;
    const int OC = OB + TBLK * 128;
    const int OD = OC + TBLK * 128;

    auto prefetch = [&](int c) {
        int t0 = c * TBLK;
        uint32_t sb = (c & 1) ? sb1 : sb0;
#pragma unroll
        for (int i = 0; i < 5; i++) {
            int it = i * 128 + tid;
            if (it < 256) {
                int t = it >> 5, q = it & 31;
                cp16(sb + (uint32_t)(OB + t * 128 + q * 4) * 4,
                     convb + (size_t)(t0 + t) * CONV_CH + D_INNER + q * 4);
            } else if (it < 512) {
                int j = it - 256;
                int t = j >> 5, q = j & 31;
                cp16(sb + (uint32_t)(OC + t * 128 + q * 4) * 4,
                     convb + (size_t)(t0 + t) * CONV_CH + D_INNER + D_STATE + q * 4);
            } else if (it < 544) {
                int j = it - 512;
                int t = j >> 2, q = j & 3;
                cp16(sb + (uint32_t)(OX + t * 16 + q * 4) * 4,
                     convb + (size_t)(t0 + t) * CONV_CH + h * HP + ps * PSL + q * 4);
            } else if (it < 548) {
                int j = it - 544;
                cp16(sb + (uint32_t)(OD + j * 4) * 4, dtAb + (size_t)t0 * 2 + j * 4);
            }
        }
    };

    const int NCHUNKS = SEQ / TBLK;

    prefetch(0);
    asm volatile("cp.async.commit_group;\n");

    for (int c = 0; c < NCHUNKS; c++) {
        if (c + 1 < NCHUNKS) prefetch(c + 1);
        asm volatile("cp.async.commit_group;\n");
        asm volatile("cp.async.wait_group 1;\n");
        __syncthreads();

        const float* stg = (c & 1) ? stage1 : stage0;
        const unsigned long long* sBu = (const unsigned long long*)(stg + OB);
        const unsigned long long* sCu = (const unsigned long long*)(stg + OC);
        const float* sdd = stg + OD;
        const float* sx  = stg + OX;

#pragma unroll
        for (int t = 0; t < TBLK; t++) {
            float dtp = sdd[t * 2];
            float dA  = sdd[t * 2 + 1];
            float dtx = dtp * sx[t * 16 + pl];
            unsigned long long dA2  = f2pack(dA, dA);
            unsigned long long dtx2 = f2pack(dtx, dtx);
            unsigned long long acc2 = 0ull;
            const ulonglong2* Bp = (const ulonglong2*)(sBu + t * 64) + nchunk * 4;
            const ulonglong2* Cp = (const ulonglong2*)(sCu + t * 64) + nchunk * 4;
#pragma unroll
            for (int j = 0; j < 4; j++) {
                ulonglong2 bq = Bp[j];
                ulonglong2 cq = Cp[j];
                st2[2*j]   = fma2(st2[2*j],   dA2, mul2(dtx2, bq.x));
                acc2       = fma2(st2[2*j],   cq.x, acc2);
                st2[2*j+1] = fma2(st2[2*j+1], dA2, mul2(dtx2, bq.y));
                acc2       = fma2(st2[2*j+1], cq.y, acc2);
            }
            syp[t * 128 + nchunk * 16 + pl] = f2sum(acc2);
        }
        __syncthreads();

        {
            int t0 = c * TBLK;
            int t  = tid >> 4;
            int pp = tid & 15;
            float v = Dh * sx[t * 16 + pp];
#pragma unroll
            for (int nc = 0; nc < 8; nc++) v += syp[t * 128 + nc * 16 + pp];
            yb[(size_t)(t0 + t) * D_INNER + pp] = v;
        }
        __syncthreads();
    }
}

// ---------------- K4: gate + RMSNorm -> bf16 split ----------------
__global__ void __launch_bounds__(256) gate_rms_kernel(
    const float* __restrict__ y, const float* __restrict__ zx,
    const float* __restrict__ nw,
    __nv_bfloat16* __restrict__ yhi, __nv_bfloat16* __restrict__ ylo)
{
    int row = blockIdx.x;
    int tid = threadIdx.x;
    const float* yr = y + (size_t)row * D_INNER;
    const float* zr = zx + (size_t)row * PROJ;
    float v0 = yr[tid], v1 = yr[tid + 256];
    float z0 = zr[tid], z1 = zr[tid + 256];
    float g0 = v0 * silu_f(z0);
    float g1 = v1 * silu_f(z1);
    float ss = block_sum256(g0 * g0 + g1 * g1);
    float r = rsqrtf(ss * (1.0f / 512.0f) + EPS);
    size_t base = (size_t)row * D_INNER;
    split_store(g0 * r * nw[tid],       yhi, ylo, base + tid);
    split_store(g1 * r * nw[tid + 256], yhi, ylo, base + tid + 256);
}

// ---------------- K5: residual add + layernorm ----------------
__global__ void __launch_bounds__(256) add_ln_kernel(
    float* __restrict__ h, const float* __restrict__ m,
    const float* __restrict__ w, const float* __restrict__ bvec,
    __nv_bfloat16* __restrict__ hhi, __nv_bfloat16* __restrict__ hlo)
{
    int row = blockIdx.x;
    int tid = threadIdx.x;
    size_t idx = (size_t)row * D_MODEL + tid;
    float v = h[idx] + m[idx];
    float mean = block_sum256(v) * (1.0f / 256.0f);
    float d = v - mean;
    float var = block_sum256(d * d) * (1.0f / 256.0f);
    float o = d * rsqrtf(var + EPS) * w[tid] + bvec[tid];
    h[idx] = o;
    split_store(o, hhi, hlo, idx);
}

// ---------------- K6: masked mean pool + classifier head ----------------
__global__ void __launch_bounds__(256) pool_head_kernel(
    const float* __restrict__ h, const int* __restrict__ lengths,
    const float* __restrict__ hw, const float* __restrict__ hb,
    float* __restrict__ out)
{
    int b = blockIdx.x;
    int tid = threadIdx.x;
    int len = lengths[b];
    const float* hr = h + (size_t)b * SEQ * D_MODEL;
    float a0 = 0.f, a1 = 0.f, a2 = 0.f, a3 = 0.f;
    int l = 0;
    for (; l + 4 <= len; l += 4) {
        a0 += hr[(size_t)(l+0) * D_MODEL + tid];
        a1 += hr[(size_t)(l+1) * D_MODEL + tid];
        a2 += hr[(size_t)(l+2) * D_MODEL + tid];
        a3 += hr[(size_t)(l+3) * D_MODEL + tid];
    }
    for (; l < len; l++) a0 += hr[(size_t)l * D_MODEL + tid];
    float acc = (a0 + a1) + (a2 + a3);
    __shared__ float sp[D_MODEL];
    sp[tid] = acc / (float)len;
    __syncthreads();
    if (tid < N_CLS) {
        float o = hb[tid];
        const float* wr = hw + (size_t)tid * D_MODEL;
#pragma unroll 8
        for (int k = 0; k < D_MODEL; k++) o = fmaf(wr[k], sp[k], o);
        out[b * N_CLS + tid] = o;
    }
}

// ---------------- launch ----------------
extern "C" void kernel_launch(void* const* d_in, const int* in_sizes, int n_in,
                              void* d_out, int out_size)
{
    const float* x        = (const float*)d_in[0];
    const float* in_w     = (const float*)d_in[1];
    const float* in_b     = (const float*)d_in[2];
    const float* lnin_w   = (const float*)d_in[3];
    const float* lnin_b   = (const float*)d_in[4];
    const float* inproj_w = (const float*)d_in[5];
    const float* conv_w   = (const float*)d_in[6];
    const float* conv_b   = (const float*)d_in[7];
    const float* dt_bias  = (const float*)d_in[8];
    const float* A_log    = (const float*)d_in[9];
    const float* Dw       = (const float*)d_in[10];
    const float* norm_w   = (const float*)d_in[11];
    const float* outp_w   = (const float*)d_in[12];
    const float* ln_w     = (const float*)d_in[13];
    const float* ln_b     = (const float*)d_in[14];
    const float* head_w   = (const float*)d_in[15];
    const float* head_b   = (const float*)d_in[16];
    const int*   lengths  = (const int*)d_in[17];
    float* out = (float*)d_out;

    float *ph, *pzx, *pconv, *py, *pm;
    float2* pdtA;
    cudaGetSymbolAddress((void**)&ph,    g_h);
    cudaGetSymbolAddress((void**)&pzx,   g_zx);
    cudaGetSymbolAddress((void**)&pconv, g_conv);
    cudaGetSymbolAddress((void**)&py,    g_y);
    cudaGetSymbolAddress((void**)&pm,    g_m);
    cudaGetSymbolAddress((void**)&pdtA,  g_dtA);
    __nv_bfloat16 *phh, *phl, *pyh, *pyl, *pwih, *pwil, *pwoh, *pwol;
    cudaGetSymbolAddress((void**)&phh,  g_hh);
    cudaGetSymbolAddress((void**)&phl,  g_hl);
    cudaGetSymbolAddress((void**)&pyh,  g_yh);
    cudaGetSymbolAddress((void**)&pyl,  g_yl);
    cudaGetSymbolAddress((void**)&pwih, g_wih);
    cudaGetSymbolAddress((void**)&pwil, g_wil);
    cudaGetSymbolAddress((void**)&pwoh, g_woh);
    cudaGetSymbolAddress((void**)&pwol, g_wol);

    cudaFuncSetAttribute(gemm_bf16_split, cudaFuncAttributeMaxDynamicSharedMemorySize, GEMM_SMEM);
    cudaFuncSetAttribute(scan_kernel, cudaFuncAttributeMaxDynamicSharedMemorySize, SCAN_SMEM);

    convert_wi_kernel<<<dim3(PROJ_PAD, NL), 256>>>(inproj_w, pwih, pwil);
    convert_wo_kernel<<<dim3(D_MODEL * D_INNER / 256, NL), 256>>>(outp_w, pwoh, pwol);

    embed_ln_kernel<<<TOKENS, 256>>>(x, in_w, in_b, lnin_w, lnin_b, ph, phh, phl);

    for (int i = 0; i < NL; i++) {
        gemm_bf16_split<<<dim3(TOKENS / 128, PROJ_PAD / 128), 256, GEMM_SMEM>>>(
            phh, phl,
            pwih + (size_t)i * PROJ_PAD * D_MODEL, pwil + (size_t)i * PROJ_PAD * D_MODEL,
            pzx, PROJ, D_MODEL);

        conv_silu_kernel<<<dim3(3, SEQ / LSEG, BATCH), 256>>>(
            pzx, conv_w + (size_t)i * DCONV * CONV_CH, conv_b + (size_t)i * CONV_CH, pconv);

        dt_kernel<<<BATCH * NH * SEQ / 256, 256>>>(
            pzx, dt_bias + i * NH, A_log + i * NH, pdtA);

        scan_kernel<<<dim3(NH, BATCH, HP / PSL), 128, SCAN_SMEM>>>(
            pconv, pdtA, Dw + i * NH, py);

        gate_rms_kernel<<<TOKENS, 256>>>(py, pzx, norm_w + (size_t)i * D_INNER, pyh, pyl);

        gemm_bf16_split<<<dim3(TOKENS / 128, D_MODEL / 128), 256, GEMM_SMEM>>>(
            pyh, pyl,
            pwoh + (size_t)i * D_MODEL * D_INNER, pwol + (size_t)i * D_MODEL * D_INNER,
            pm, D_MODEL, D_INNER);

        add_ln_kernel<<<TOKENS, 256>>>(ph, pm, ln_w + (size_t)i * D_MODEL,
                                       ln_b + (size_t)i * D_MODEL, phh, phl);
    }

    pool_head_kernel<<<BATCH, 256>>>(ph, lengths, head_w, head_b, out);
}